// round 2
// baseline (speedup 1.0000x reference)
#include <cuda_runtime.h>
#include <cstdint>

#define D 128
#define NMAX 50000
#define NPAD 50176   // padded rows so OOB tile loads stay in-bounds

// Scratch (__device__ globals per allocation rules)
__device__ __align__(16) float g_h[NPAD * D];     // feature + aggregated neighbors
__device__ __align__(16) float g_y1[NPAD * D];    // hidden layer
__device__ __align__(16) float g_w1t[D * D];      // W1 transposed [col][k]
__device__ __align__(16) float g_w2t[D * D];      // W2 transposed [col][k]
__device__ __align__(16) float g_stats[2 * D];    // col sums/sumsq -> scale/shift

// ---------------------------------------------------------------------------
__device__ __forceinline__ void fma2(double& acc, double a, double b) {
    asm("fma.rn.f32x2 %0, %1, %2, %0;" : "+d"(acc) : "d"(a), "d"(b));
}
__device__ __forceinline__ void unpack2(double d, float& lo, float& hi) {
    asm("mov.b64 {%0, %1}, %2;" : "=f"(lo), "=f"(hi) : "d"(d));
}
__device__ __forceinline__ void cp16(uint32_t dst, const void* src) {
    asm volatile("cp.async.cg.shared.global [%0], [%1], 16;" :: "r"(dst), "l"(src));
}
__device__ __forceinline__ void cp_commit() {
    asm volatile("cp.async.commit_group;");
}
template <int N>
__device__ __forceinline__ void cp_wait() {
    asm volatile("cp.async.wait_group %0;" :: "n"(N));
}

// ---------------------------------------------------------------------------
// Kernel 1: h = feature (GIN eps = 0); zero BN stats
// ---------------------------------------------------------------------------
__global__ void k_init(const float4* __restrict__ feat, int n4) {
    int i = blockIdx.x * blockDim.x + threadIdx.x;
    if (i < n4) reinterpret_cast<float4*>(g_h)[i] = feat[i];
    if (blockIdx.x == 0 && threadIdx.x < 2 * D) g_stats[threadIdx.x] = 0.0f;
}

// ---------------------------------------------------------------------------
// Kernel 2: transpose both weight matrices (one-shot, tiny)
// ---------------------------------------------------------------------------
__global__ void k_wt(const float* __restrict__ W1, const float* __restrict__ W2) {
    int i = blockIdx.x * 256 + threadIdx.x;
    if (i < D * D) {
        int k = i >> 7, c = i & 127;
        g_w1t[c * D + k] = W1[i];
        g_w2t[c * D + k] = W2[i];
    }
}

// ---------------------------------------------------------------------------
// Kernel 3: scatter-add. One warp per edge; red.global.add.v4.f32 per lane.
// ---------------------------------------------------------------------------
__global__ void k_scatter(const float* __restrict__ feat,
                          const int* __restrict__ ei, int E) {
    int gw = (blockIdx.x * blockDim.x + threadIdx.x) >> 5;
    int lane = threadIdx.x & 31;
    if (gw >= E) return;
    int src = __ldg(ei + gw);
    int dst = __ldg(ei + E + gw);
    const float4 v = reinterpret_cast<const float4*>(feat + (size_t)src * D)[lane];
    float* p = g_h + (size_t)dst * D + lane * 4;
    asm volatile("red.global.add.v4.f32 [%0], {%1, %2, %3, %4};"
                 :: "l"(p), "f"(v.x), "f"(v.y), "f"(v.z), "f"(v.w)
                 : "memory");
}

// ---------------------------------------------------------------------------
// Kernel 4/5: C = relu(A @ W + b). A [M,128], Wt [128 cols][128 k].
// 512 threads, block tile 128x128, thread tile 8 rows x 4 cols, BK=32.
// k-paired f32x2 accumulators: operands load as double2 straight from SMEM
// (zero pack MOVs). Double-buffered cp.async pipeline.
// ---------------------------------------------------------------------------
template <bool STATS>
__global__ __launch_bounds__(512, 1)
void k_gemm(float* __restrict__ outp, const float* __restrict__ bias, int M) {
    const float* __restrict__ Aglob = STATS ? g_y1 : g_h;
    const float* __restrict__ Wt    = STATS ? g_w2t : g_w1t;
    float* __restrict__ C           = STATS ? outp : g_y1;

    __shared__ __align__(16) float As[2][128][36];
    __shared__ __align__(16) float Bs[2][128][36];

    const int tid = threadIdx.x;
    const int tx = tid & 31;          // lane: col group (cols 32j+tx)
    const int ty = tid >> 5;          // warp: row group (rows 8ty..8ty+7)
    const int rowBase = blockIdx.x * 128;

    const uint32_t asBase = (uint32_t)__cvta_generic_to_shared(&As[0][0][0]);
    const uint32_t bsBase = (uint32_t)__cvta_generic_to_shared(&Bs[0][0][0]);
    const uint32_t bufStride = 128u * 36u * 4u;

    double acc[8][4];
#pragma unroll
    for (int i = 0; i < 8; ++i)
#pragma unroll
        for (int j = 0; j < 4; ++j) acc[i][j] = 0.0;

    // cp.async fill of one (A,B) tile pair into buffer b
    auto issueTile = [&](int kt, int b) {
#pragma unroll
        for (int t = 0; t < 2; ++t) {
            int f = tid + t * 512;
            int r = f >> 3;                 // row (A) / col (B)
            int k4 = (f & 7) * 4;           // k offset
            cp16(asBase + b * bufStride + (uint32_t)(r * 36 + k4) * 4,
                 Aglob + (size_t)(rowBase + r) * D + kt * 32 + k4);
            cp16(bsBase + b * bufStride + (uint32_t)(r * 36 + k4) * 4,
                 Wt + (size_t)r * D + kt * 32 + k4);
        }
        cp_commit();
    };

    issueTile(0, 0);
#pragma unroll
    for (int kt = 0; kt < 4; ++kt) {
        const int cb = kt & 1;
        if (kt < 3) {
            issueTile(kt + 1, cb ^ 1);
            cp_wait<1>();
        } else {
            cp_wait<0>();
        }
        __syncthreads();

#pragma unroll
        for (int kk = 0; kk < 32; kk += 4) {
            const double2 B0 = *reinterpret_cast<const double2*>(&Bs[cb][tx][kk]);
            const double2 B1 = *reinterpret_cast<const double2*>(&Bs[cb][32 + tx][kk]);
            const double2 B2 = *reinterpret_cast<const double2*>(&Bs[cb][64 + tx][kk]);
            const double2 B3 = *reinterpret_cast<const double2*>(&Bs[cb][96 + tx][kk]);
#pragma unroll
            for (int i = 0; i < 8; ++i) {
                const double2 Ai =
                    *reinterpret_cast<const double2*>(&As[cb][ty * 8 + i][kk]);
                fma2(acc[i][0], Ai.x, B0.x); fma2(acc[i][0], Ai.y, B0.y);
                fma2(acc[i][1], Ai.x, B1.x); fma2(acc[i][1], Ai.y, B1.y);
                fma2(acc[i][2], Ai.x, B2.x); fma2(acc[i][2], Ai.y, B2.y);
                fma2(acc[i][3], Ai.x, B3.x); fma2(acc[i][3], Ai.y, B3.y);
            }
        }
        __syncthreads();
    }

    // Epilogue: bias + relu + store (+ optional BN stats)
    float bj[4];
#pragma unroll
    for (int j = 0; j < 4; ++j) bj[j] = __ldg(bias + 32 * j + tx);

    float cs[4] = {0.f, 0.f, 0.f, 0.f};
    float cq[4] = {0.f, 0.f, 0.f, 0.f};

#pragma unroll
    for (int i = 0; i < 8; ++i) {
        int row = rowBase + ty * 8 + i;
        if (row < M) {
#pragma unroll
            for (int j = 0; j < 4; ++j) {
                float e, o;
                unpack2(acc[i][j], e, o);
                float v = fmaxf(e + o + bj[j], 0.f);
                C[(size_t)row * D + 32 * j + tx] = v;
                if (STATS) { cs[j] += v; cq[j] += v * v; }
            }
        }
    }

    if (STATS) {
        float* Red = &As[0][0][0];  // reuse SMEM (all tile reads done)
#pragma unroll
        for (int j = 0; j < 4; ++j) Red[ty * 128 + 32 * j + tx] = cs[j];
        __syncthreads();
        if (tid < 128) {
            float s = 0.f;
#pragma unroll
            for (int t = 0; t < 16; ++t) s += Red[t * 128 + tid];
            atomicAdd(&g_stats[tid], s);
        }
        __syncthreads();
#pragma unroll
        for (int j = 0; j < 4; ++j) Red[ty * 128 + 32 * j + tx] = cq[j];
        __syncthreads();
        if (tid < 128) {
            float s = 0.f;
#pragma unroll
            for (int t = 0; t < 16; ++t) s += Red[t * 128 + tid];
            atomicAdd(&g_stats[128 + tid], s);
        }
    }
}

// ---------------------------------------------------------------------------
// Kernel 6: (sum, sumsq) -> (scale, shift). 1 block, 128 threads.
// ---------------------------------------------------------------------------
__global__ void k_finalize(const float* __restrict__ gamma,
                           const float* __restrict__ beta, float invN) {
    int c = threadIdx.x;
    float mean = g_stats[c] * invN;
    float var = g_stats[128 + c] * invN - mean * mean;
    float scale = gamma[c] * rsqrtf(var + 1e-5f);
    g_stats[c] = scale;
    g_stats[128 + c] = beta[c] - mean * scale;
}

// ---------------------------------------------------------------------------
// Kernel 7: out = out * scale[col] + shift[col], in place, float4.
// ---------------------------------------------------------------------------
__global__ void k_norm(float4* __restrict__ out, int n4) {
    int i = blockIdx.x * blockDim.x + threadIdx.x;
    if (i >= n4) return;
    int c4 = (i & 31) * 4;
    float4 sc = *reinterpret_cast<const float4*>(&g_stats[c4]);
    float4 sh = *reinterpret_cast<const float4*>(&g_stats[128 + c4]);
    float4 v = out[i];
    v.x = v.x * sc.x + sh.x;
    v.y = v.y * sc.y + sh.y;
    v.z = v.z * sc.z + sh.z;
    v.w = v.w * sc.w + sh.w;
    out[i] = v;
}

// ---------------------------------------------------------------------------
extern "C" void kernel_launch(void* const* d_in, const int* in_sizes, int n_in,
                              void* d_out, int out_size) {
    const float* feat  = (const float*)d_in[0];
    const int*   ei    = (const int*)d_in[1];
    const float* W1    = (const float*)d_in[2];
    const float* b1    = (const float*)d_in[3];
    const float* W2    = (const float*)d_in[4];
    const float* b2    = (const float*)d_in[5];
    const float* gamma = (const float*)d_in[6];
    const float* beta  = (const float*)d_in[7];
    float* out = (float*)d_out;

    const int N = in_sizes[0] / D;     // 50000
    const int E = in_sizes[1] / 2;     // 600000
    const int n4 = N * D / 4;

    k_init<<<(n4 + 255) / 256, 256>>>((const float4*)feat, n4);
    k_wt<<<(D * D + 255) / 256, 256>>>(W1, W2);
    {
        long long totalThreads = (long long)E * 32;
        int blocks = (int)((totalThreads + 255) / 256);
        k_scatter<<<blocks, 256>>>(feat, ei, E);
    }
    int gb = (N + 127) / 128;          // 391
    k_gemm<false><<<gb, 512>>>(nullptr, b1, N);
    k_gemm<true><<<gb, 512>>>(out, b2, N);
    k_finalize<<<1, 128>>>(gamma, beta, 1.0f / (float)N);
    k_norm<<<(n4 + 255) / 256, 256>>>((float4*)out, n4);
}

// round 4
// speedup vs baseline: 1.1296x; 1.1296x over previous
#include <cuda_runtime.h>
#include <cuda_bf16.h>
#include <cstdint>

#define D 128
#define NMAX 50000
#define NPAD 50176   // >= 391*128, pad rows stay zero (module zero-init, never written)

// ---------------------------------------------------------------------------
// Scratch (__device__ globals per allocation rules)
// ---------------------------------------------------------------------------
__device__ __align__(16) float         g_h[NPAD * D];     // feat + aggregation (f32)
__device__ __align__(16) __nv_bfloat16 g_hA[NPAD * D];    // split hi of g_h
__device__ __align__(16) __nv_bfloat16 g_hB[NPAD * D];    // split lo of g_h
__device__ __align__(16) __nv_bfloat16 g_y1h[NPAD * D];   // hidden hi
__device__ __align__(16) __nv_bfloat16 g_y1l[NPAD * D];   // hidden lo
__device__ __align__(16) __nv_bfloat16 g_w1tH[D * D];     // W1^T hi [col][k]
__device__ __align__(16) __nv_bfloat16 g_w1tL[D * D];     // W1^T lo
__device__ __align__(16) __nv_bfloat16 g_w2tH[D * D];     // W2^T hi
__device__ __align__(16) __nv_bfloat16 g_w2tL[D * D];     // W2^T lo
__device__ __align__(16) float         g_stats[2 * D];    // col sum/sumsq -> scale/shift

// ---------------------------------------------------------------------------
// PTX helpers (portable ISA only — no tcgen05 on this build target)
// ---------------------------------------------------------------------------
__device__ __forceinline__ void cp16(uint32_t dst, const void* src) {
    asm volatile("cp.async.cg.shared.global [%0], [%1], 16;" :: "r"(dst), "l"(src));
}
__device__ __forceinline__ void cp_commit() { asm volatile("cp.async.commit_group;"); }
template <int N>
__device__ __forceinline__ void cp_wait() {
    asm volatile("cp.async.wait_group %0;" :: "n"(N));
}
__device__ __forceinline__ uint32_t smem_u32(const void* p) {
    return (uint32_t)__cvta_generic_to_shared(p);
}
__device__ __forceinline__ void mma16816(float* c, const uint32_t* a, const uint32_t* b) {
    asm volatile(
        "mma.sync.aligned.m16n8k16.row.col.f32.bf16.bf16.f32 "
        "{%0,%1,%2,%3}, {%4,%5,%6,%7}, {%8,%9}, {%0,%1,%2,%3};"
        : "+f"(c[0]), "+f"(c[1]), "+f"(c[2]), "+f"(c[3])
        : "r"(a[0]), "r"(a[1]), "r"(a[2]), "r"(a[3]), "r"(b[0]), "r"(b[1]));
}

// SMEM tile geometry: 128 rows x 128 k halves, padded row stride 136 halves
// (68 words) -> fragment LDS bank = (4*g + l4) mod 32, conflict-free.
#define SH 136
#define TILE_HALVES (128 * SH)          // 17408 halves = 34816 B
#define TILE_BYTES (TILE_HALVES * 2)

// ---------------------------------------------------------------------------
// Kernel 1: h = feature (GIN eps=0); zero BN stats
// ---------------------------------------------------------------------------
__global__ void k_init(const float4* __restrict__ feat, int n4) {
    int i = blockIdx.x * blockDim.x + threadIdx.x;
    if (i < n4) reinterpret_cast<float4*>(g_h)[i] = feat[i];
    if (blockIdx.x == 0 && threadIdx.x < 2 * D) g_stats[threadIdx.x] = 0.0f;
}

// ---------------------------------------------------------------------------
// Kernel 2: transpose + bf16-split both weight matrices (one-shot, tiny)
// ---------------------------------------------------------------------------
__global__ void k_wt(const float* __restrict__ W1, const float* __restrict__ W2) {
    int i = blockIdx.x * 256 + threadIdx.x;
    if (i < D * D) {
        int k = i >> 7, c = i & 127;
        float w1 = W1[i], w2 = W2[i];
        __nv_bfloat16 h1 = __float2bfloat16(w1);
        __nv_bfloat16 h2 = __float2bfloat16(w2);
        g_w1tH[c * D + k] = h1;
        g_w1tL[c * D + k] = __float2bfloat16(w1 - __bfloat162float(h1));
        g_w2tH[c * D + k] = h2;
        g_w2tL[c * D + k] = __float2bfloat16(w2 - __bfloat162float(h2));
    }
}

// ---------------------------------------------------------------------------
// Kernel 3: scatter-add. One warp per edge; red.global.add.v4.f32 per lane.
// ---------------------------------------------------------------------------
__global__ void k_scatter(const float* __restrict__ feat,
                          const int* __restrict__ ei, int E) {
    int gw = (blockIdx.x * blockDim.x + threadIdx.x) >> 5;
    int lane = threadIdx.x & 31;
    if (gw >= E) return;
    int src = __ldg(ei + gw);
    int dst = __ldg(ei + E + gw);
    const float4 v = reinterpret_cast<const float4*>(feat + (size_t)src * D)[lane];
    float* p = g_h + (size_t)dst * D + lane * 4;
    asm volatile("red.global.add.v4.f32 [%0], {%1, %2, %3, %4};"
                 :: "l"(p), "f"(v.x), "f"(v.y), "f"(v.z), "f"(v.w)
                 : "memory");
}

// ---------------------------------------------------------------------------
// Kernel 4: split g_h (f32) -> g_hA (bf16 hi) + g_hB (bf16 lo)
// ---------------------------------------------------------------------------
__global__ void k_split(int n4) {
    int i = blockIdx.x * blockDim.x + threadIdx.x;
    if (i >= n4) return;
    float4 v = reinterpret_cast<const float4*>(g_h)[i];
    __nv_bfloat162 h01 = __floats2bfloat162_rn(v.x, v.y);
    __nv_bfloat162 h23 = __floats2bfloat162_rn(v.z, v.w);
    __nv_bfloat162 l01 = __floats2bfloat162_rn(v.x - __bfloat162float(h01.x),
                                               v.y - __bfloat162float(h01.y));
    __nv_bfloat162 l23 = __floats2bfloat162_rn(v.z - __bfloat162float(h23.x),
                                               v.w - __bfloat162float(h23.y));
    uint2 hv, lv;
    hv.x = *reinterpret_cast<uint32_t*>(&h01);
    hv.y = *reinterpret_cast<uint32_t*>(&h23);
    lv.x = *reinterpret_cast<uint32_t*>(&l01);
    lv.y = *reinterpret_cast<uint32_t*>(&l23);
    reinterpret_cast<uint2*>(g_hA)[i] = hv;
    reinterpret_cast<uint2*>(g_hB)[i] = lv;
}

// ---------------------------------------------------------------------------
// Kernel 5/6: tensor-core GEMM via mma.sync (m16n8k16 bf16 -> f32).
// C = relu(A @ W + b) with 3-term split: AhWh + AhWl + AlWh.
// 256 threads = 8 warps (4 m-groups x 2 n-groups), warp tile 32x64.
// All 4 tiles (Ah, Al, Bh, Bl) staged once via cp.async; 24 k16 steps.
// ---------------------------------------------------------------------------
template <bool FIRST>
__global__ __launch_bounds__(256, 1)
void k_mma(const float* __restrict__ bias, float* __restrict__ outF, int M) {
    extern __shared__ __align__(16) uint8_t smem[];
    uint16_t* sAh = reinterpret_cast<uint16_t*>(smem);
    uint16_t* sAl = sAh + TILE_HALVES;
    uint16_t* sBh = sAl + TILE_HALVES;
    uint16_t* sBl = sBh + TILE_HALVES;
    float* s_bias = reinterpret_cast<float*>(sBl + TILE_HALVES);

    const __nv_bfloat16* __restrict__ Ah = FIRST ? g_hA : g_y1h;
    const __nv_bfloat16* __restrict__ Al = FIRST ? g_hB : g_y1l;
    const __nv_bfloat16* __restrict__ Bh = FIRST ? g_w1tH : g_w2tH;
    const __nv_bfloat16* __restrict__ Bl = FIRST ? g_w1tL : g_w2tL;

    const int tid = threadIdx.x;
    const int wid = tid >> 5;
    const int lane = tid & 31;
    const int g = lane >> 2;        // fragment row group 0..7
    const int l4 = lane & 3;        // fragment k group 0..3
    const int warpM = wid & 3;      // 4 m-groups of 32 rows
    const int warpN = wid >> 2;     // 2 n-groups of 64 cols
    const int rowBase = blockIdx.x * 128;

    if (tid < D) s_bias[tid] = bias[tid];

    // Stage all 4 tiles: dst row stride 272B, global rows dense 256B.
    const uint32_t sBase = smem_u32(smem);
#pragma unroll
    for (int t = 0; t < 8; ++t) {
        int idx = tid + t * 256;            // 0..2047
        int row = idx >> 4;                 // 0..127
        int kb = (idx & 15) * 16;           // byte col 0..240
        uint32_t dOff = (uint32_t)(row * (SH * 2) + kb);
        size_t gA = (size_t)(rowBase + row) * 256 + kb;
        size_t gB = (size_t)row * 256 + kb;
        cp16(sBase + dOff,                  (const uint8_t*)Ah + gA);
        cp16(sBase + TILE_BYTES + dOff,     (const uint8_t*)Al + gA);
        cp16(sBase + 2 * TILE_BYTES + dOff, (const uint8_t*)Bh + gB);
        cp16(sBase + 3 * TILE_BYTES + dOff, (const uint8_t*)Bl + gB);
    }
    cp_commit();
    cp_wait<0>();
    __syncthreads();

    float c[2][8][4];
#pragma unroll
    for (int mi = 0; mi < 2; ++mi)
#pragma unroll
        for (int ni = 0; ni < 8; ++ni)
#pragma unroll
            for (int e = 0; e < 4; ++e) c[mi][ni][e] = 0.f;

    const int aRow = warpM * 32 + g;
    const int bRow = warpN * 64 + g;
    const int kcol = 2 * l4;

#pragma unroll
    for (int pass = 0; pass < 3; ++pass) {
        const uint16_t* At = (pass == 2) ? sAl : sAh;
        const uint16_t* Bt = (pass == 1) ? sBl : sBh;
#pragma unroll
        for (int ks = 0; ks < 8; ++ks) {
            const int kc = ks * 16 + kcol;
            uint32_t a[2][4], b[8][2];
#pragma unroll
            for (int mi = 0; mi < 2; ++mi) {
                const int r = aRow + mi * 16;
                a[mi][0] = *reinterpret_cast<const uint32_t*>(&At[r * SH + kc]);
                a[mi][1] = *reinterpret_cast<const uint32_t*>(&At[(r + 8) * SH + kc]);
                a[mi][2] = *reinterpret_cast<const uint32_t*>(&At[r * SH + kc + 8]);
                a[mi][3] = *reinterpret_cast<const uint32_t*>(&At[(r + 8) * SH + kc + 8]);
            }
#pragma unroll
            for (int ni = 0; ni < 8; ++ni) {
                const int r = bRow + ni * 8;
                b[ni][0] = *reinterpret_cast<const uint32_t*>(&Bt[r * SH + kc]);
                b[ni][1] = *reinterpret_cast<const uint32_t*>(&Bt[r * SH + kc + 8]);
            }
#pragma unroll
            for (int mi = 0; mi < 2; ++mi)
#pragma unroll
                for (int ni = 0; ni < 8; ++ni)
                    mma16816(c[mi][ni], a[mi], b[ni]);
        }
    }

    // Epilogue: bias + relu; FIRST -> bf16 hi/lo split to y1, else f32 out.
#pragma unroll
    for (int mi = 0; mi < 2; ++mi) {
#pragma unroll
        for (int half = 0; half < 2; ++half) {
            const int row = rowBase + warpM * 32 + mi * 16 + g + half * 8;
            if (row < M) {
#pragma unroll
                for (int ni = 0; ni < 8; ++ni) {
                    const int col = warpN * 64 + ni * 8 + 2 * l4;
                    float v0 = fmaxf(c[mi][ni][half * 2 + 0] + s_bias[col], 0.f);
                    float v1 = fmaxf(c[mi][ni][half * 2 + 1] + s_bias[col + 1], 0.f);
                    if (FIRST) {
                        __nv_bfloat16 h0 = __float2bfloat16(v0);
                        __nv_bfloat16 h1 = __float2bfloat16(v1);
                        __nv_bfloat162 hh; hh.x = h0; hh.y = h1;
                        __nv_bfloat162 ll = __floats2bfloat162_rn(
                            v0 - __bfloat162float(h0), v1 - __bfloat162float(h1));
                        size_t bo = (size_t)row * 256 + (size_t)col * 2;
                        *reinterpret_cast<uint32_t*>((uint8_t*)g_y1h + bo) =
                            *reinterpret_cast<uint32_t*>(&hh);
                        *reinterpret_cast<uint32_t*>((uint8_t*)g_y1l + bo) =
                            *reinterpret_cast<uint32_t*>(&ll);
                    } else {
                        float2 st; st.x = v0; st.y = v1;
                        *reinterpret_cast<float2*>(outF + (size_t)row * D + col) = st;
                    }
                }
            }
        }
    }
}

// ---------------------------------------------------------------------------
// Kernel 7: column sums / sumsq of d_out (pre-normalization y)
// ---------------------------------------------------------------------------
__global__ void k_stats(const float* __restrict__ out, int M) {
    int base = blockIdx.x * 128;
    int c = threadIdx.x;
    float s = 0.f, q = 0.f;
#pragma unroll 4
    for (int r = 0; r < 128; ++r) {
        int row = base + r;
        if (row < M) {
            float v = out[(size_t)row * D + c];
            s += v;
            q += v * v;
        }
    }
    atomicAdd(&g_stats[c], s);
    atomicAdd(&g_stats[D + c], q);
}

// ---------------------------------------------------------------------------
// Kernel 8: (sum, sumsq) -> (scale, shift)
// ---------------------------------------------------------------------------
__global__ void k_finalize(const float* __restrict__ gamma,
                           const float* __restrict__ beta, float invN) {
    int c = threadIdx.x;
    float mean = g_stats[c] * invN;
    float var = g_stats[D + c] * invN - mean * mean;
    float scale = gamma[c] * rsqrtf(var + 1e-5f);
    g_stats[c] = scale;
    g_stats[D + c] = beta[c] - mean * scale;
}

// ---------------------------------------------------------------------------
// Kernel 9: out = out * scale[col] + shift[col], in place
// ---------------------------------------------------------------------------
__global__ void k_norm(float4* __restrict__ out, int n4) {
    int i = blockIdx.x * blockDim.x + threadIdx.x;
    if (i >= n4) return;
    int c4 = (i & 31) * 4;
    float4 sc = *reinterpret_cast<const float4*>(&g_stats[c4]);
    float4 sh = *reinterpret_cast<const float4*>(&g_stats[D + c4]);
    float4 v = out[i];
    v.x = v.x * sc.x + sh.x;
    v.y = v.y * sc.y + sh.y;
    v.z = v.z * sc.z + sh.z;
    v.w = v.w * sc.w + sh.w;
    out[i] = v;
}

// ---------------------------------------------------------------------------
extern "C" void kernel_launch(void* const* d_in, const int* in_sizes, int n_in,
                              void* d_out, int out_size) {
    const float* feat  = (const float*)d_in[0];
    const int*   ei    = (const int*)d_in[1];
    const float* W1    = (const float*)d_in[2];
    const float* b1    = (const float*)d_in[3];
    const float* W2    = (const float*)d_in[4];
    const float* b2    = (const float*)d_in[5];
    const float* gamma = (const float*)d_in[6];
    const float* beta  = (const float*)d_in[7];
    float* out = (float*)d_out;

    const int N = in_sizes[0] / D;     // 50000
    const int E = in_sizes[1] / 2;     // 600000
    const int n4 = N * D / 4;

    const int smemBytes = 4 * TILE_BYTES + 512;   // 139,776 B
    cudaFuncSetAttribute(k_mma<true>, cudaFuncAttributeMaxDynamicSharedMemorySize, smemBytes);
    cudaFuncSetAttribute(k_mma<false>, cudaFuncAttributeMaxDynamicSharedMemorySize, smemBytes);

    k_init<<<(n4 + 255) / 256, 256>>>((const float4*)feat, n4);
    k_wt<<<(D * D + 255) / 256, 256>>>(W1, W2);
    {
        long long totalThreads = (long long)E * 32;
        int blocks = (int)((totalThreads + 255) / 256);
        k_scatter<<<blocks, 256>>>(feat, ei, E);
    }
    k_split<<<(n4 + 255) / 256, 256>>>(n4);
    int gb = (N + 127) / 128;          // 391
    k_mma<true><<<gb, 256, smemBytes>>>(b1, nullptr, N);
    k_mma<false><<<gb, 256, smemBytes>>>(b2, out, N);
    k_stats<<<gb, 128>>>(out, N);
    k_finalize<<<1, 128>>>(gamma, beta, 1.0f / (float)N);
    k_norm<<<(n4 + 255) / 256, 256>>>((float4*)out, n4);
}

// round 5
// speedup vs baseline: 1.2411x; 1.0987x over previous
#include <cuda_runtime.h>
#include <cuda_bf16.h>
#include <cstdint>

#define D 128
#define NMAX 50000
#define NPAD 50176   // >= 391*128; pad rows of scratch stay zero (never written)

// ---------------------------------------------------------------------------
// Scratch (__device__ globals per allocation rules)
// ---------------------------------------------------------------------------
__device__ __align__(16) float         g_agg[NPAD * D];   // neighbor sum (zeroed each run)
__device__ __align__(16) __nv_bfloat16 g_y1h[NPAD * D];   // hidden hi
__device__ __align__(16) __nv_bfloat16 g_y1l[NPAD * D];   // hidden lo
__device__ __align__(16) __nv_bfloat16 g_w1tH[D * D];     // W1^T hi [col][k]
__device__ __align__(16) __nv_bfloat16 g_w1tL[D * D];     // W1^T lo
__device__ __align__(16) __nv_bfloat16 g_w2tH[D * D];     // W2^T hi
__device__ __align__(16) __nv_bfloat16 g_w2tL[D * D];     // W2^T lo
__device__ __align__(16) float         g_stats[2 * D];    // col sum/sumsq -> scale/shift

// ---------------------------------------------------------------------------
// PTX helpers (portable ISA only — tcgen05 unavailable on compute_103 target)
// ---------------------------------------------------------------------------
__device__ __forceinline__ void cp16(uint32_t dst, const void* src) {
    asm volatile("cp.async.cg.shared.global [%0], [%1], 16;" :: "r"(dst), "l"(src));
}
__device__ __forceinline__ void cp_commit() { asm volatile("cp.async.commit_group;"); }
template <int N>
__device__ __forceinline__ void cp_wait() {
    asm volatile("cp.async.wait_group %0;" :: "n"(N));
}
__device__ __forceinline__ uint32_t smem_u32(const void* p) {
    return (uint32_t)__cvta_generic_to_shared(p);
}
__device__ __forceinline__ void mma16816(float* c, const uint32_t* a, const uint32_t* b) {
    asm volatile(
        "mma.sync.aligned.m16n8k16.row.col.f32.bf16.bf16.f32 "
        "{%0,%1,%2,%3}, {%4,%5,%6,%7}, {%8,%9}, {%0,%1,%2,%3};"
        : "+f"(c[0]), "+f"(c[1]), "+f"(c[2]), "+f"(c[3])
        : "r"(a[0]), "r"(a[1]), "r"(a[2]), "r"(a[3]), "r"(b[0]), "r"(b[1]));
}

// SMEM tile: 128 rows x 128 k halves, padded row stride 136 halves -> LDS
// fragment reads are bank-conflict-free.
#define SH 136
#define TILE_HALVES (128 * SH)
#define TILE_BYTES (TILE_HALVES * 2)    // 34816

// ---------------------------------------------------------------------------
// Kernel 1: zero aggregation buffer + BN stats (replaces copy-init)
// ---------------------------------------------------------------------------
__global__ void k_zero(int n4) {
    int i = blockIdx.x * blockDim.x + threadIdx.x;
    if (i < n4) reinterpret_cast<float4*>(g_agg)[i] = make_float4(0.f, 0.f, 0.f, 0.f);
    if (blockIdx.x == 0 && threadIdx.x < 2 * D) g_stats[threadIdx.x] = 0.0f;
}

// ---------------------------------------------------------------------------
// Kernel 2: transpose + bf16-split both weight matrices (one-shot, tiny)
// ---------------------------------------------------------------------------
__global__ void k_wt(const float* __restrict__ W1, const float* __restrict__ W2) {
    int i = blockIdx.x * 256 + threadIdx.x;
    if (i < D * D) {
        int k = i >> 7, c = i & 127;
        float w1 = W1[i], w2 = W2[i];
        __nv_bfloat16 h1 = __float2bfloat16(w1);
        __nv_bfloat16 h2 = __float2bfloat16(w2);
        g_w1tH[c * D + k] = h1;
        g_w1tL[c * D + k] = __float2bfloat16(w1 - __bfloat162float(h1));
        g_w2tH[c * D + k] = h2;
        g_w2tL[c * D + k] = __float2bfloat16(w2 - __bfloat162float(h2));
    }
}

// ---------------------------------------------------------------------------
// Kernel 3: scatter-add. One warp per edge; red.global.add.v4.f32 per lane.
// ---------------------------------------------------------------------------
__global__ void k_scatter(const float* __restrict__ feat,
                          const int* __restrict__ ei, int E) {
    int gw = (blockIdx.x * blockDim.x + threadIdx.x) >> 5;
    int lane = threadIdx.x & 31;
    if (gw >= E) return;
    int src = __ldg(ei + gw);
    int dst = __ldg(ei + E + gw);
    const float4 v = reinterpret_cast<const float4*>(feat + (size_t)src * D)[lane];
    float* p = g_agg + (size_t)dst * D + lane * 4;
    asm volatile("red.global.add.v4.f32 [%0], {%1, %2, %3, %4};"
                 :: "l"(p), "f"(v.x), "f"(v.y), "f"(v.z), "f"(v.w)
                 : "memory");
}

// ---------------------------------------------------------------------------
// Kernel 4/5: tensor-core GEMM via mma.sync (m16n8k16 bf16 -> f32).
// C = relu(A @ W + b), 3-term split AhWh + AhWl + AlWh.
// FIRST: A = feat + g_agg (f32, converted+split in prologue), out -> y1 hi/lo.
// !FIRST: A = y1 hi/lo via cp.async, out -> d_out f32 + fused BN stats.
// 256 threads = 8 warps (4 m-groups x 2 n-groups), warp tile 32x64.
// ---------------------------------------------------------------------------
template <bool FIRST>
__global__ __launch_bounds__(256, 1)
void k_mma(const float* __restrict__ feat, const float* __restrict__ bias,
           float* __restrict__ outF, int M) {
    extern __shared__ __align__(16) uint8_t smem[];
    uint16_t* sAh = reinterpret_cast<uint16_t*>(smem);
    uint16_t* sAl = sAh + TILE_HALVES;
    uint16_t* sBh = sAl + TILE_HALVES;
    uint16_t* sBl = sBh + TILE_HALVES;
    float* s_bias = reinterpret_cast<float*>(sBl + TILE_HALVES);

    const __nv_bfloat16* __restrict__ Bh = FIRST ? g_w1tH : g_w2tH;
    const __nv_bfloat16* __restrict__ Bl = FIRST ? g_w1tL : g_w2tL;

    const int tid = threadIdx.x;
    const int wid = tid >> 5;
    const int lane = tid & 31;
    const int g = lane >> 2;
    const int l4 = lane & 3;
    const int warpM = wid & 3;
    const int warpN = wid >> 2;
    const int rowBase = blockIdx.x * 128;

    if (tid < D) s_bias[tid] = bias[tid];

    const uint32_t sBase = smem_u32(smem);

    // ---- B tiles: always cp.async ----
#pragma unroll
    for (int t = 0; t < 8; ++t) {
        int idx = tid + t * 256;            // 0..2047
        int row = idx >> 4;                 // 0..127
        int kb = (idx & 15) * 16;           // byte col 0..240
        uint32_t dOff = (uint32_t)(row * (SH * 2) + kb);
        size_t gB = (size_t)row * 256 + kb;
        cp16(sBase + 2 * TILE_BYTES + dOff, (const uint8_t*)Bh + gB);
        cp16(sBase + 3 * TILE_BYTES + dOff, (const uint8_t*)Bl + gB);
    }
    cp_commit();

    // ---- A tiles ----
    if (FIRST) {
        // load feat+agg (f32), convert to bf16 hi/lo, STS.128
#pragma unroll
        for (int t = 0; t < 8; ++t) {
            int idx = tid + t * 256;        // 0..2047 = 128 rows x 16 chunks
            int row = idx >> 4;
            int kc = (idx & 15) * 8;        // k offset (halves/floats)
            int grow = rowBase + row;
            float h[8];
            if (grow < M) {
                const float4* fp = reinterpret_cast<const float4*>(feat + (size_t)grow * D + kc);
                const float4* ap = reinterpret_cast<const float4*>(g_agg + (size_t)grow * D + kc);
                float4 f0 = fp[0], f1 = fp[1], a0 = ap[0], a1 = ap[1];
                h[0] = f0.x + a0.x; h[1] = f0.y + a0.y; h[2] = f0.z + a0.z; h[3] = f0.w + a0.w;
                h[4] = f1.x + a1.x; h[5] = f1.y + a1.y; h[6] = f1.z + a1.z; h[7] = f1.w + a1.w;
            } else {
#pragma unroll
                for (int e = 0; e < 8; ++e) h[e] = 0.f;
            }
            uint4 hv, lv;
            uint32_t* hp = reinterpret_cast<uint32_t*>(&hv);
            uint32_t* lp = reinterpret_cast<uint32_t*>(&lv);
#pragma unroll
            for (int e = 0; e < 4; ++e) {
                __nv_bfloat162 hh = __floats2bfloat162_rn(h[2 * e], h[2 * e + 1]);
                __nv_bfloat162 ll = __floats2bfloat162_rn(
                    h[2 * e] - __bfloat162float(hh.x),
                    h[2 * e + 1] - __bfloat162float(hh.y));
                hp[e] = *reinterpret_cast<uint32_t*>(&hh);
                lp[e] = *reinterpret_cast<uint32_t*>(&ll);
            }
            *reinterpret_cast<uint4*>(&sAh[row * SH + kc]) = hv;
            *reinterpret_cast<uint4*>(&sAl[row * SH + kc]) = lv;
        }
    } else {
#pragma unroll
        for (int t = 0; t < 8; ++t) {
            int idx = tid + t * 256;
            int row = idx >> 4;
            int kb = (idx & 15) * 16;
            uint32_t dOff = (uint32_t)(row * (SH * 2) + kb);
            size_t gA = (size_t)(rowBase + row) * 256 + kb;
            cp16(sBase + dOff,              (const uint8_t*)g_y1h + gA);
            cp16(sBase + TILE_BYTES + dOff, (const uint8_t*)g_y1l + gA);
        }
        cp_commit();
    }
    cp_wait<0>();
    __syncthreads();

    // ---- MMA mainloop ----
    float c[2][8][4];
#pragma unroll
    for (int mi = 0; mi < 2; ++mi)
#pragma unroll
        for (int ni = 0; ni < 8; ++ni)
#pragma unroll
            for (int e = 0; e < 4; ++e) c[mi][ni][e] = 0.f;

    const int aRow = warpM * 32 + g;
    const int bRow = warpN * 64 + g;
    const int kcol = 2 * l4;

#pragma unroll
    for (int pass = 0; pass < 3; ++pass) {
        const uint16_t* At = (pass == 2) ? sAl : sAh;
        const uint16_t* Bt = (pass == 1) ? sBl : sBh;
#pragma unroll
        for (int ks = 0; ks < 8; ++ks) {
            const int kc = ks * 16 + kcol;
            uint32_t a[2][4], b[8][2];
#pragma unroll
            for (int mi = 0; mi < 2; ++mi) {
                const int r = aRow + mi * 16;
                a[mi][0] = *reinterpret_cast<const uint32_t*>(&At[r * SH + kc]);
                a[mi][1] = *reinterpret_cast<const uint32_t*>(&At[(r + 8) * SH + kc]);
                a[mi][2] = *reinterpret_cast<const uint32_t*>(&At[r * SH + kc + 8]);
                a[mi][3] = *reinterpret_cast<const uint32_t*>(&At[(r + 8) * SH + kc + 8]);
            }
#pragma unroll
            for (int ni = 0; ni < 8; ++ni) {
                const int r = bRow + ni * 8;
                b[ni][0] = *reinterpret_cast<const uint32_t*>(&Bt[r * SH + kc]);
                b[ni][1] = *reinterpret_cast<const uint32_t*>(&Bt[r * SH + kc + 8]);
            }
#pragma unroll
            for (int mi = 0; mi < 2; ++mi)
#pragma unroll
                for (int ni = 0; ni < 8; ++ni)
                    mma16816(c[mi][ni], a[mi], b[ni]);
        }
    }

    // ---- Epilogue ----
    float cs[8][2], cq[8][2];
    if (!FIRST) {
#pragma unroll
        for (int ni = 0; ni < 8; ++ni) {
            cs[ni][0] = cs[ni][1] = 0.f;
            cq[ni][0] = cq[ni][1] = 0.f;
        }
    }

#pragma unroll
    for (int mi = 0; mi < 2; ++mi) {
#pragma unroll
        for (int half = 0; half < 2; ++half) {
            const int row = rowBase + warpM * 32 + mi * 16 + g + half * 8;
            if (row < M) {
#pragma unroll
                for (int ni = 0; ni < 8; ++ni) {
                    const int col = warpN * 64 + ni * 8 + 2 * l4;
                    float v0 = fmaxf(c[mi][ni][half * 2 + 0] + s_bias[col], 0.f);
                    float v1 = fmaxf(c[mi][ni][half * 2 + 1] + s_bias[col + 1], 0.f);
                    if (FIRST) {
                        __nv_bfloat16 h0 = __float2bfloat16(v0);
                        __nv_bfloat16 h1 = __float2bfloat16(v1);
                        __nv_bfloat162 hh; hh.x = h0; hh.y = h1;
                        __nv_bfloat162 ll = __floats2bfloat162_rn(
                            v0 - __bfloat162float(h0), v1 - __bfloat162float(h1));
                        size_t bo = (size_t)row * 256 + (size_t)col * 2;
                        *reinterpret_cast<uint32_t*>((uint8_t*)g_y1h + bo) =
                            *reinterpret_cast<uint32_t*>(&hh);
                        *reinterpret_cast<uint32_t*>((uint8_t*)g_y1l + bo) =
                            *reinterpret_cast<uint32_t*>(&ll);
                    } else {
                        float2 st; st.x = v0; st.y = v1;
                        *reinterpret_cast<float2*>(outF + (size_t)row * D + col) = st;
                        cs[ni][0] += v0; cs[ni][1] += v1;
                        cq[ni][0] += v0 * v0; cq[ni][1] += v1 * v1;
                    }
                }
            }
        }
    }

    if (!FIRST) {
        // reduce over g-lanes (lane bits 2..4) via shfl_xor
#pragma unroll
        for (int off = 4; off < 32; off <<= 1) {
#pragma unroll
            for (int ni = 0; ni < 8; ++ni) {
#pragma unroll
                for (int e = 0; e < 2; ++e) {
                    cs[ni][e] += __shfl_xor_sync(0xFFFFFFFFu, cs[ni][e], off);
                    cq[ni][e] += __shfl_xor_sync(0xFFFFFFFFu, cq[ni][e], off);
                }
            }
        }
        __syncthreads();                 // staging tiles dead; reuse as reduction buffer
        float* redS = reinterpret_cast<float*>(smem);            // [8][64]
        float* redQ = redS + 8 * 64;                             // [8][64]
        if (g == 0) {                    // lanes 0..3 hold reduced values
#pragma unroll
            for (int ni = 0; ni < 8; ++ni) {
#pragma unroll
                for (int e = 0; e < 2; ++e) {
                    int cc = ni * 8 + 2 * l4 + e;   // col within warpN half
                    redS[wid * 64 + cc] = cs[ni][e];
                    redQ[wid * 64 + cc] = cq[ni][e];
                }
            }
        }
        __syncthreads();
        if (tid < 128) {
            int wBase = (tid < 64) ? 0 : 4;      // warpN: warps 0-3 cols 0-63, 4-7 cols 64-127
            int cc = tid & 63;
            float s = 0.f, q = 0.f;
#pragma unroll
            for (int w = 0; w < 4; ++w) {
                s += redS[(wBase + w) * 64 + cc];
                q += redQ[(wBase + w) * 64 + cc];
            }
            atomicAdd(&g_stats[tid], s);
            atomicAdd(&g_stats[D + tid], q);
        }
    }
}

// ---------------------------------------------------------------------------
// Kernel 6: (sum, sumsq) -> (scale, shift)
// ---------------------------------------------------------------------------
__global__ void k_finalize(const float* __restrict__ gamma,
                           const float* __restrict__ beta, float invN) {
    int c = threadIdx.x;
    float mean = g_stats[c] * invN;
    float var = g_stats[D + c] * invN - mean * mean;
    float scale = gamma[c] * rsqrtf(var + 1e-5f);
    g_stats[c] = scale;
    g_stats[D + c] = beta[c] - mean * scale;
}

// ---------------------------------------------------------------------------
// Kernel 7: out = out * scale[col] + shift[col], in place
// ---------------------------------------------------------------------------
__global__ void k_norm(float4* __restrict__ out, int n4) {
    int i = blockIdx.x * blockDim.x + threadIdx.x;
    if (i >= n4) return;
    int c4 = (i & 31) * 4;
    float4 sc = *reinterpret_cast<const float4*>(&g_stats[c4]);
    float4 sh = *reinterpret_cast<const float4*>(&g_stats[D + c4]);
    float4 v = out[i];
    v.x = v.x * sc.x + sh.x;
    v.y = v.y * sc.y + sh.y;
    v.z = v.z * sc.z + sh.z;
    v.w = v.w * sc.w + sh.w;
    out[i] = v;
}

// ---------------------------------------------------------------------------
extern "C" void kernel_launch(void* const* d_in, const int* in_sizes, int n_in,
                              void* d_out, int out_size) {
    const float* feat  = (const float*)d_in[0];
    const int*   ei    = (const int*)d_in[1];
    const float* W1    = (const float*)d_in[2];
    const float* b1    = (const float*)d_in[3];
    const float* W2    = (const float*)d_in[4];
    const float* b2    = (const float*)d_in[5];
    const float* gamma = (const float*)d_in[6];
    const float* beta  = (const float*)d_in[7];
    float* out = (float*)d_out;

    const int N = in_sizes[0] / D;     // 50000
    const int E = in_sizes[1] / 2;     // 600000
    const int n4 = N * D / 4;

    const int smemBytes = 4 * TILE_BYTES + 512;   // 139,776 B
    cudaFuncSetAttribute(k_mma<true>, cudaFuncAttributeMaxDynamicSharedMemorySize, smemBytes);
    cudaFuncSetAttribute(k_mma<false>, cudaFuncAttributeMaxDynamicSharedMemorySize, smemBytes);

    k_zero<<<(n4 + 255) / 256, 256>>>(n4);
    k_wt<<<(D * D + 255) / 256, 256>>>(W1, W2);
    {
        long long totalThreads = (long long)E * 32;
        int blocks = (int)((totalThreads + 255) / 256);
        k_scatter<<<blocks, 256>>>(feat, ei, E);
    }
    int gb = (N + 127) / 128;          // 391
    k_mma<true><<<gb, 256, smemBytes>>>(feat, b1, nullptr, N);
    k_mma<false><<<gb, 256, smemBytes>>>(nullptr, b2, out, N);
    k_finalize<<<1, 128>>>(gamma, beta, 1.0f / (float)N);
    k_norm<<<(n4 + 255) / 256, 256>>>((float4*)out, n4);
}